// round 2
// baseline (speedup 1.0000x reference)
#include <cuda_runtime.h>
#include <cstdint>

#define BB 128
#define SS 50
#define XX 128
#define HH 256
#define VV 10000
#define MM (BB*SS)   // 6400

// Scratch (device globals: no allocation allowed in kernel_launch)
__device__ float g_xin[MM * HH];   // input projection, [B,S,H] flattened (m-major)
__device__ float g_hs [MM * HH];   // hidden states,    [B,S,H] flattened (m-major)

// ---------- packed fp32x2 helpers ----------
__device__ __forceinline__ double dup2(float x) {
    double r; asm("mov.b64 %0, {%1, %1};" : "=d"(r) : "f"(x)); return r;
}
__device__ __forceinline__ double pk2(float lo, float hi) {
    double r; asm("mov.b64 %0, {%1, %2};" : "=d"(r) : "f"(lo), "f"(hi)); return r;
}
__device__ __forceinline__ float2 unpk(double d) {
    float2 f; asm("mov.b64 {%0, %1}, %2;" : "=f"(f.x), "=f"(f.y) : "d"(d)); return f;
}
__device__ __forceinline__ void ffma2(double& acc, double a, double b) {
    asm("fma.rn.f32x2 %0, %1, %2, %0;" : "+d"(acc) : "d"(a), "d"(b));
}

// ============================================================================
// Kernel A: embedding gather + input projection
//   g_xin[m][j] = dot(emb[x[m]], W_ih[j,:]) + b_ih[j] + b_hh[j]
// One block = 32 rows (m), 256 threads (one output column j each).
// ============================================================================
__global__ void __launch_bounds__(256)
embed_proj(const int* __restrict__ xraw,
           const float* __restrict__ emb,
           const float* __restrict__ W_ih,
           const float* __restrict__ b_ih,
           const float* __restrict__ b_hh)
{
    __shared__ __align__(16) float se[32][XX];

    // Detect int64 vs int32 token buffer (jax x64 off -> int32).
    // int64 little-endian: odd int32 words are zero high-halves.
    const bool is64 = ((xraw[1] | xraw[3] | xraw[5] | xraw[7] | xraw[9]) == 0) &&
                      ((xraw[0] | xraw[2] | xraw[4] | xraw[6] | xraw[8]) != 0);

    const int m0 = blockIdx.x * 32;

    // gather 32 embedding rows into smem: 32 * 32 float4
    for (int i = threadIdx.x; i < 32 * (XX / 4); i += 256) {
        int r = i >> 5;
        int c = i & 31;
        int m = m0 + r;
        int tok = is64 ? xraw[2 * m] : xraw[m];
        ((float4*)se[r])[c] = ((const float4*)(emb + (long long)tok * XX))[c];
    }
    __syncthreads();

    const int j = threadIdx.x;
    const float bias = b_ih[j] + b_hh[j];
    float acc[32];
#pragma unroll
    for (int r = 0; r < 32; r++) acc[r] = bias;

    const float* wr = W_ih + j * XX;
#pragma unroll 4
    for (int k = 0; k < XX; k += 4) {
        float4 w = *(const float4*)(wr + k);
#pragma unroll
        for (int r = 0; r < 32; r++) {
            float4 e = *(const float4*)&se[r][k];
            acc[r] = fmaf(w.x, e.x, fmaf(w.y, e.y, fmaf(w.z, e.z, fmaf(w.w, e.w, acc[r]))));
        }
    }
#pragma unroll
    for (int r = 0; r < 32; r++)
        g_xin[(m0 + r) * HH + j] = acc[r];
}

// ============================================================================
// Kernel B: RNN scan. 32 CTAs, each owns 4 batch rows. 256 threads = one
// output unit j each. h double-buffered in smem as float4 (4 rows packed).
//   h_new[r][j] = tanh(xin[b0+r][t][j] + dot(W_hh[j,:], h_old[r][:]))
// Packed f32x2 FMAs: rows (0,1) and (2,3) share each W scalar.
// ============================================================================
__global__ void __launch_bounds__(256)
rnn_scan(const float* __restrict__ W_hh)
{
    __shared__ __align__(16) float4 hbuf[2][HH];

    const int j  = threadIdx.x;
    const int b0 = blockIdx.x * 4;

    hbuf[0][j] = make_float4(0.f, 0.f, 0.f, 0.f);
    __syncthreads();

    const float* wr = W_hh + j * HH;
    const float* xin0 = g_xin + (b0 + 0) * SS * HH + j;
    const float* xin1 = g_xin + (b0 + 1) * SS * HH + j;
    const float* xin2 = g_xin + (b0 + 2) * SS * HH + j;
    const float* xin3 = g_xin + (b0 + 3) * SS * HH + j;
    float* hs0 = g_hs + (b0 + 0) * SS * HH + j;
    float* hs1 = g_hs + (b0 + 1) * SS * HH + j;
    float* hs2 = g_hs + (b0 + 2) * SS * HH + j;
    float* hs3 = g_hs + (b0 + 3) * SS * HH + j;

    int cur = 0;
    for (int t = 0; t < SS; ++t) {
        double a01 = pk2(xin0[t * HH], xin1[t * HH]);
        double a23 = pk2(xin2[t * HH], xin3[t * HH]);

        const float4* hc = hbuf[cur];
#pragma unroll 8
        for (int k = 0; k < HH; k += 4) {
            float4 w = *(const float4*)(wr + k);
            double2 p0 = *(const double2*)(hc + k + 0);
            double2 p1 = *(const double2*)(hc + k + 1);
            double2 p2 = *(const double2*)(hc + k + 2);
            double2 p3 = *(const double2*)(hc + k + 3);
            double w0 = dup2(w.x), w1 = dup2(w.y), w2 = dup2(w.z), w3 = dup2(w.w);
            ffma2(a01, w0, p0.x); ffma2(a23, w0, p0.y);
            ffma2(a01, w1, p1.x); ffma2(a23, w1, p1.y);
            ffma2(a01, w2, p2.x); ffma2(a23, w2, p2.y);
            ffma2(a01, w3, p3.x); ffma2(a23, w3, p3.y);
        }

        float2 f01 = unpk(a01), f23 = unpk(a23);
        float h0 = tanhf(f01.x), h1 = tanhf(f01.y);
        float h2 = tanhf(f23.x), h3 = tanhf(f23.y);

        hbuf[cur ^ 1][j] = make_float4(h0, h1, h2, h3);
        hs0[t * HH] = h0; hs1[t * HH] = h1; hs2[t * HH] = h2; hs3[t * HH] = h3;

        cur ^= 1;
        __syncthreads();
    }
}

// ============================================================================
// Kernel C: output GEMM  C[m][n] = dot(g_hs[m,:], W_aff[n,:]) + b_aff[n]
//   M=6400, N=10000, K=256. Both operands K-major -> transpose into smem.
// Tile 128x128, BK=16, 256 threads, 8x8 microtile via packed fma.rn.f32x2.
// A stored in smem PRE-DUPLICATED as f32x2 pairs (no per-iter dup MOVs).
// ============================================================================
__global__ void __launch_bounds__(256, 2)
out_gemm(const float* __restrict__ Wa,
         const float* __restrict__ ba,
         float* __restrict__ C)
{
    __shared__ __align__(16) double Asd[16][128];  // dup'd A: 16 KB
    __shared__ __align__(16) float  Bs [16][128];  // 8 KB

    const int tid  = threadIdx.x;
    const int bm   = blockIdx.y * 128;
    const int bn   = blockIdx.x * 128;
    const int tcol = tid & 15;
    const int trow = tid >> 4;
    const int tm   = trow * 8;
    const int tn   = tcol * 8;

    // loader mapping: 128 rows x 16 k, each thread loads 8 floats of one row
    const int lr = tid & 127;
    const int lk = (tid >> 7) * 8;
    const float* Ap = g_hs + (bm + lr) * HH + lk;
    const int   gb = bn + lr;
    const bool  bvalid = (gb < VV);
    const float* Bp = Wa + (long long)(bvalid ? gb : 0) * HH + lk;

    double acc[8][4];
#pragma unroll
    for (int i = 0; i < 8; i++)
#pragma unroll
        for (int jq = 0; jq < 4; jq++) acc[i][jq] = 0.0;

    for (int kt = 0; kt < HH; kt += 16) {
        float4 a0 = *(const float4*)(Ap + kt);
        float4 a1 = *(const float4*)(Ap + kt + 4);
        float4 b0, b1;
        if (bvalid) {
            b0 = *(const float4*)(Bp + kt);
            b1 = *(const float4*)(Bp + kt + 4);
        } else {
            b0 = make_float4(0.f, 0.f, 0.f, 0.f);
            b1 = b0;
        }
        __syncthreads();
        Asd[lk + 0][lr] = dup2(a0.x); Asd[lk + 1][lr] = dup2(a0.y);
        Asd[lk + 2][lr] = dup2(a0.z); Asd[lk + 3][lr] = dup2(a0.w);
        Asd[lk + 4][lr] = dup2(a1.x); Asd[lk + 5][lr] = dup2(a1.y);
        Asd[lk + 6][lr] = dup2(a1.z); Asd[lk + 7][lr] = dup2(a1.w);
        Bs[lk + 0][lr] = b0.x; Bs[lk + 1][lr] = b0.y;
        Bs[lk + 2][lr] = b0.z; Bs[lk + 3][lr] = b0.w;
        Bs[lk + 4][lr] = b1.x; Bs[lk + 5][lr] = b1.y;
        Bs[lk + 6][lr] = b1.z; Bs[lk + 7][lr] = b1.w;
        __syncthreads();

#pragma unroll
        for (int kk = 0; kk < 16; ++kk) {
            double2 aa0 = *(const double2*)&Asd[kk][tm + 0];
            double2 aa1 = *(const double2*)&Asd[kk][tm + 2];
            double2 aa2 = *(const double2*)&Asd[kk][tm + 4];
            double2 aa3 = *(const double2*)&Asd[kk][tm + 6];
            double2 bb0 = *(const double2*)&Bs[kk][tn + 0];
            double2 bb1 = *(const double2*)&Bs[kk][tn + 4];
            double av[8] = {aa0.x, aa0.y, aa1.x, aa1.y, aa2.x, aa2.y, aa3.x, aa3.y};
            double bv[4] = {bb0.x, bb0.y, bb1.x, bb1.y};
#pragma unroll
            for (int i = 0; i < 8; i++)
#pragma unroll
                for (int jq = 0; jq < 4; jq++)
                    ffma2(acc[i][jq], av[i], bv[jq]);
        }
    }

    // epilogue: unpack, add bias, guarded float4 stores
    const int gm = bm + tm;
    const int gn = bn + tn;
    float bb[8];
#pragma unroll
    for (int jj = 0; jj < 8; jj++)
        bb[jj] = (gn + jj < VV) ? ba[gn + jj] : 0.f;

#pragma unroll
    for (int i = 0; i < 8; i++) {
        float o[8];
#pragma unroll
        for (int jq = 0; jq < 4; jq++) {
            float2 f = unpk(acc[i][jq]);
            o[2 * jq + 0] = f.x + bb[2 * jq + 0];
            o[2 * jq + 1] = f.y + bb[2 * jq + 1];
        }
        float* cp = C + (size_t)(gm + i) * VV + gn;
        if (gn + 4 <= VV) *(float4*)(cp + 0) = make_float4(o[0], o[1], o[2], o[3]);
        if (gn + 8 <= VV) *(float4*)(cp + 4) = make_float4(o[4], o[5], o[6], o[7]);
    }
}

// ============================================================================
extern "C" void kernel_launch(void* const* d_in, const int* in_sizes, int n_in,
                              void* d_out, int out_size)
{
    const int*   x     = (const int*)  d_in[0];  // int32 or int64 (auto-detected)
    const float* emb   = (const float*)d_in[1];
    const float* W_ih  = (const float*)d_in[2];
    const float* W_hh  = (const float*)d_in[3];
    const float* b_ih  = (const float*)d_in[4];
    const float* b_hh  = (const float*)d_in[5];
    const float* W_aff = (const float*)d_in[6];
    const float* b_aff = (const float*)d_in[7];
    float* out = (float*)d_out;

    embed_proj<<<MM / 32, 256>>>(x, emb, W_ih, b_ih, b_hh);
    rnn_scan<<<BB / 4, 256>>>(W_hh);
    dim3 gC((VV + 127) / 128, MM / 128);
    out_gemm<<<gC, 256>>>(W_aff, b_aff, out);
}

// round 4
// speedup vs baseline: 1.8224x; 1.8224x over previous
#include <cuda_runtime.h>
#include <cuda_bf16.h>
#include <cstdint>

#define BB 128
#define SS 50
#define XX 128
#define HH 256
#define VV 10000
#define MM (BB*SS)     // 6400
#define NPAD 10240     // VV padded to N-tile multiple

// ---------------- device scratch (no allocs allowed in kernel_launch) ------
__device__ float g_xin[MM * HH];                         // input projection
__device__ __align__(16) __nv_bfloat16 g_A2[MM * 512];   // [m][0:256]=hi, [256:512]=lo of h
__device__ __align__(16) __nv_bfloat16 g_B2[(size_t)NPAD * 512]; // same split of W_aff

// ---------------- packed fp32x2 helpers (rnn) -------------------------------
__device__ __forceinline__ double dup2(float x) {
    double r; asm("mov.b64 %0, {%1, %1};" : "=d"(r) : "f"(x)); return r;
}
__device__ __forceinline__ double pk2(float lo, float hi) {
    double r; asm("mov.b64 %0, {%1, %2};" : "=d"(r) : "f"(lo), "f"(hi)); return r;
}
__device__ __forceinline__ float2 unpk(double d) {
    float2 f; asm("mov.b64 {%0, %1}, %2;" : "=f"(f.x), "=f"(f.y) : "d"(d)); return f;
}
__device__ __forceinline__ void ffma2(double& acc, double a, double b) {
    asm("fma.rn.f32x2 %0, %1, %2, %0;" : "+d"(acc) : "d"(a), "d"(b));
}

// ---------------- mma / smem helpers ----------------------------------------
__device__ __forceinline__ uint32_t smem_u32(const void* p) {
    uint32_t a;
    asm("{ .reg .u64 t; cvta.to.shared.u64 t, %1; cvt.u32.u64 %0, t; }" : "=r"(a) : "l"(p));
    return a;
}
__device__ __forceinline__ void cp_async16(uint32_t dst, const void* src) {
    asm volatile("cp.async.cg.shared.global [%0], [%1], 16;"
                 :: "r"(dst), "l"(src) : "memory");
}
__device__ __forceinline__ void ldsm4(uint32_t r[4], uint32_t addr) {
    asm volatile("ldmatrix.sync.aligned.m8n8.x4.shared.b16 {%0,%1,%2,%3}, [%4];"
                 : "=r"(r[0]), "=r"(r[1]), "=r"(r[2]), "=r"(r[3]) : "r"(addr));
}
__device__ __forceinline__ void mma16816(float c[4], const uint32_t a[4],
                                         uint32_t b0, uint32_t b1) {
    asm volatile(
        "mma.sync.aligned.m16n8k16.row.col.f32.bf16.bf16.f32 "
        "{%0,%1,%2,%3}, {%4,%5,%6,%7}, {%8,%9}, {%0,%1,%2,%3};"
        : "+f"(c[0]), "+f"(c[1]), "+f"(c[2]), "+f"(c[3])
        : "r"(a[0]), "r"(a[1]), "r"(a[2]), "r"(a[3]), "r"(b0), "r"(b1));
}
#define SW128(x) ((x) ^ (((x) >> 3) & 0x70))

__device__ __forceinline__ void store_split(__nv_bfloat16* p, float v) {
    __nv_bfloat16 hi = __float2bfloat16(v);
    p[0]   = hi;
    p[256] = __float2bfloat16(v - __bfloat162float(hi));
}

// ============================================================================
// Kernel A: embedding gather + input projection
// ============================================================================
__global__ void __launch_bounds__(256)
embed_proj(const int* __restrict__ xraw,
           const float* __restrict__ emb,
           const float* __restrict__ W_ih,
           const float* __restrict__ b_ih,
           const float* __restrict__ b_hh)
{
    __shared__ __align__(16) float se[32][XX];

    const bool is64 = ((xraw[1] | xraw[3] | xraw[5] | xraw[7] | xraw[9]) == 0) &&
                      ((xraw[0] | xraw[2] | xraw[4] | xraw[6] | xraw[8]) != 0);

    const int m0 = blockIdx.x * 32;
    for (int i = threadIdx.x; i < 32 * (XX / 4); i += 256) {
        int r = i >> 5, c = i & 31;
        int m = m0 + r;
        int tok = is64 ? xraw[2 * m] : xraw[m];
        ((float4*)se[r])[c] = ((const float4*)(emb + (long long)tok * XX))[c];
    }
    __syncthreads();

    const int j = threadIdx.x;
    const float bias = b_ih[j] + b_hh[j];
    float acc[32];
#pragma unroll
    for (int r = 0; r < 32; r++) acc[r] = bias;

    const float* wr = W_ih + j * XX;
#pragma unroll 4
    for (int k = 0; k < XX; k += 4) {
        float4 w = *(const float4*)(wr + k);
#pragma unroll
        for (int r = 0; r < 32; r++) {
            float4 e = *(const float4*)&se[r][k];
            acc[r] = fmaf(w.x, e.x, fmaf(w.y, e.y, fmaf(w.z, e.z, fmaf(w.w, e.w, acc[r]))));
        }
    }
#pragma unroll
    for (int r = 0; r < 32; r++)
        g_xin[(m0 + r) * HH + j] = acc[r];
}

// ============================================================================
// Kernel B: RNN scan — emits split-bf16 hidden states into g_A2
// ============================================================================
__global__ void __launch_bounds__(256)
rnn_scan(const float* __restrict__ W_hh)
{
    __shared__ __align__(16) float4 hbuf[2][HH];

    const int j  = threadIdx.x;
    const int b0 = blockIdx.x * 4;

    hbuf[0][j] = make_float4(0.f, 0.f, 0.f, 0.f);
    __syncthreads();

    const float* wr = W_hh + j * HH;
    const float* xin0 = g_xin + (b0 + 0) * SS * HH + j;
    const float* xin1 = g_xin + (b0 + 1) * SS * HH + j;
    const float* xin2 = g_xin + (b0 + 2) * SS * HH + j;
    const float* xin3 = g_xin + (b0 + 3) * SS * HH + j;
    __nv_bfloat16* a0 = g_A2 + (size_t)(b0 + 0) * SS * 512 + j;
    __nv_bfloat16* a1 = g_A2 + (size_t)(b0 + 1) * SS * 512 + j;
    __nv_bfloat16* a2 = g_A2 + (size_t)(b0 + 2) * SS * 512 + j;
    __nv_bfloat16* a3 = g_A2 + (size_t)(b0 + 3) * SS * 512 + j;

    int cur = 0;
    for (int t = 0; t < SS; ++t) {
        double p01 = pk2(xin0[t * HH], xin1[t * HH]);
        double p23 = pk2(xin2[t * HH], xin3[t * HH]);

        const float4* hc = hbuf[cur];
#pragma unroll 8
        for (int k = 0; k < HH; k += 4) {
            float4 w = *(const float4*)(wr + k);
            double2 q0 = *(const double2*)(hc + k + 0);
            double2 q1 = *(const double2*)(hc + k + 1);
            double2 q2 = *(const double2*)(hc + k + 2);
            double2 q3 = *(const double2*)(hc + k + 3);
            double w0 = dup2(w.x), w1 = dup2(w.y), w2 = dup2(w.z), w3 = dup2(w.w);
            ffma2(p01, w0, q0.x); ffma2(p23, w0, q0.y);
            ffma2(p01, w1, q1.x); ffma2(p23, w1, q1.y);
            ffma2(p01, w2, q2.x); ffma2(p23, w2, q2.y);
            ffma2(p01, w3, q3.x); ffma2(p23, w3, q3.y);
        }

        float2 f01 = unpk(p01), f23 = unpk(p23);
        float h0 = tanhf(f01.x), h1 = tanhf(f01.y);
        float h2 = tanhf(f23.x), h3 = tanhf(f23.y);

        hbuf[cur ^ 1][j] = make_float4(h0, h1, h2, h3);
        store_split(a0 + (size_t)t * 512, h0);
        store_split(a1 + (size_t)t * 512, h1);
        store_split(a2 + (size_t)t * 512, h2);
        store_split(a3 + (size_t)t * 512, h3);

        cur ^= 1;
        __syncthreads();
    }
}

// ============================================================================
// Kernel C0: split W_aff -> g_B2 (hi|lo bf16), zero-padded rows to NPAD
// ============================================================================
__global__ void __launch_bounds__(256)
split_w(const float* __restrict__ Wa)
{
    int idx = blockIdx.x * 256 + threadIdx.x;    // NPAD * 64 threads
    int n  = idx >> 6;
    int k4 = (idx & 63) << 2;
    float4 w = make_float4(0.f, 0.f, 0.f, 0.f);
    if (n < VV) w = *(const float4*)(Wa + (size_t)n * 256 + k4);
    __nv_bfloat16* p = g_B2 + (size_t)n * 512 + k4;
    __nv_bfloat16 h0 = __float2bfloat16(w.x);
    __nv_bfloat16 h1 = __float2bfloat16(w.y);
    __nv_bfloat16 h2 = __float2bfloat16(w.z);
    __nv_bfloat16 h3 = __float2bfloat16(w.w);
    p[0] = h0; p[1] = h1; p[2] = h2; p[3] = h3;
    p[256] = __float2bfloat16(w.x - __bfloat162float(h0));
    p[257] = __float2bfloat16(w.y - __bfloat162float(h1));
    p[258] = __float2bfloat16(w.z - __bfloat162float(h2));
    p[259] = __float2bfloat16(w.w - __bfloat162float(h3));
}

// ============================================================================
// Kernel C: bf16-split output GEMM on tensor cores via mma.sync (m16n8k16)
//   C[m][n] = A_hi.B_hi + A_lo.B_hi + A_hi.B_lo + b_aff[n]
// CTA tile 128x128, 8 warps (4Mx2N), warptile 32x64, K-chunks of 64,
// SW128-swizzled smem + ldmatrix.x4, cp.async double buffering.
// ============================================================================
#define TILE_BYTES 16384              // 128 rows x 128 bytes (64 bf16)
#define BUF_BYTES  (2 * TILE_BYTES)   // A + B per stage
#define SMEM_GEMM  (2 * BUF_BYTES)    // double buffered = 65536

__global__ void __launch_bounds__(256, 2)
out_gemm_mma(const float* __restrict__ ba, float* __restrict__ C)
{
    extern __shared__ __align__(1024) char smem[];
    const uint32_t sb = smem_u32(smem);

    const int tid  = threadIdx.x;
    const int wid  = tid >> 5;
    const int lane = tid & 31;
    const int bm   = blockIdx.y * 128;
    const int bn   = blockIdx.x * 128;

    // ---- loader geometry: 4 x 16B per thread per tile ----
    uint32_t a_sw[4], b_sw[4];
    const __nv_bfloat16* a_src[4];
    const __nv_bfloat16* b_src[4];
#pragma unroll
    for (int i = 0; i < 4; i++) {
        int idx = i * 256 + tid, row = idx >> 3, c = idx & 7;
        uint32_t sw = SW128(row * 128 + c * 16);
        a_sw[i] = sw;
        b_sw[i] = sw;
        a_src[i] = g_A2 + (size_t)(bm + row) * 512 + c * 8;
        b_src[i] = g_B2 + (size_t)(bn + row) * 512 + c * 8;
    }

    // ---- per-lane ldmatrix geometry ----
    const int wm0 = (wid >> 1) * 32;          // warp M origin (0..96)
    const int wn0 = (wid & 1) * 64;           // warp N origin (0 or 64)
    // A: lanes 0-7 m0-7/k0, 8-15 m8-15/k0, 16-23 m0-7/k16, 24-31 m8-15/k16
    const int a_row  = wm0 + (lane & 7) + ((lane & 8) ? 8 : 0);
    const int a_koff = (lane & 16) ? 16 : 0;
    // B: lanes 0-7 n0-7/k0, 8-15 n0-7/k16, 16-23 n8-15/k0, 24-31 n8-15/k16
    const int b_row  = wn0 + (lane & 7) + ((lane & 16) ? 8 : 0);
    const int b_koff = (lane & 8) ? 16 : 0;

    float acc[2][8][4];
#pragma unroll
    for (int mt = 0; mt < 2; mt++)
#pragma unroll
        for (int nt = 0; nt < 8; nt++)
#pragma unroll
            for (int q = 0; q < 4; q++) acc[mt][nt][q] = 0.f;

    // ---- chunk prefetch: seg 0: Ahi.Bhi, 1: Alo.Bhi, 2: Ahi.Blo ----
    auto prefetch = [&](int ch) {
        const int seg = ch >> 2, s = ch & 3;
        const int aoff = ((seg == 1) ? 256 : 0) + s * 64;
        const int boff = ((seg == 2) ? 256 : 0) + s * 64;
        const uint32_t base = sb + (ch & 1) * BUF_BYTES;
#pragma unroll
        for (int i = 0; i < 4; i++) cp_async16(base + a_sw[i], a_src[i] + aoff);
#pragma unroll
        for (int i = 0; i < 4; i++) cp_async16(base + TILE_BYTES + b_sw[i], b_src[i] + boff);
        asm volatile("cp.async.commit_group;" ::: "memory");
    };

    prefetch(0);

#pragma unroll 1
    for (int ch = 0; ch < 12; ++ch) {
        if (ch + 1 < 12) prefetch(ch + 1);
        if (ch + 1 < 12) asm volatile("cp.async.wait_group 1;" ::: "memory");
        else             asm volatile("cp.async.wait_group 0;" ::: "memory");
        __syncthreads();

        const uint32_t Ab = sb + (ch & 1) * BUF_BYTES;
        const uint32_t Bb = Ab + TILE_BYTES;

#pragma unroll
        for (int ks = 0; ks < 4; ++ks) {
            const int kb = ks * 32;   // bytes within 128B row
            uint32_t a[2][4], b[4][4];
#pragma unroll
            for (int mt = 0; mt < 2; mt++)
                ldsm4(a[mt], Ab + SW128((a_row + mt * 16) * 128 + kb + a_koff));
#pragma unroll
            for (int p = 0; p < 4; p++)
                ldsm4(b[p], Bb + SW128((b_row + p * 16) * 128 + kb + b_koff));
#pragma unroll
            for (int mt = 0; mt < 2; mt++)
#pragma unroll
                for (int p = 0; p < 4; p++) {
                    mma16816(acc[mt][2 * p + 0], a[mt], b[p][0], b[p][1]);
                    mma16816(acc[mt][2 * p + 1], a[mt], b[p][2], b[p][3]);
                }
        }
        __syncthreads();
    }

    // ---- epilogue: direct register-fragment stores with bias ----
    const int lm = lane >> 2;
    const int lq = (lane & 3) * 2;
#pragma unroll
    for (int nt = 0; nt < 8; nt++) {
        const int gcol = bn + wn0 + nt * 8 + lq;
        if (gcol >= VV) continue;
        const float2 bv = *(const float2*)(ba + gcol);
#pragma unroll
        for (int mt = 0; mt < 2; mt++) {
            const int row = bm + wm0 + mt * 16 + lm;
            float* c0 = C + (size_t)row * VV + gcol;
            float2 o0 = make_float2(acc[mt][nt][0] + bv.x, acc[mt][nt][1] + bv.y);
            float2 o1 = make_float2(acc[mt][nt][2] + bv.x, acc[mt][nt][3] + bv.y);
            *(float2*)c0            = o0;
            *(float2*)(c0 + 8 * VV) = o1;
        }
    }
}

// ============================================================================
extern "C" void kernel_launch(void* const* d_in, const int* in_sizes, int n_in,
                              void* d_out, int out_size)
{
    const int*   x     = (const int*)  d_in[0];
    const float* emb   = (const float*)d_in[1];
    const float* W_ih  = (const float*)d_in[2];
    const float* W_hh  = (const float*)d_in[3];
    const float* b_ih  = (const float*)d_in[4];
    const float* b_hh  = (const float*)d_in[5];
    const float* W_aff = (const float*)d_in[6];
    const float* b_aff = (const float*)d_in[7];
    float* out = (float*)d_out;

    cudaFuncSetAttribute(out_gemm_mma, cudaFuncAttributeMaxDynamicSharedMemorySize, SMEM_GEMM);

    embed_proj<<<MM / 32, 256>>>(x, emb, W_ih, b_ih, b_hh);
    split_w<<<(NPAD * 64) / 256, 256>>>(W_aff);
    rnn_scan<<<BB / 4, 256>>>(W_hh);
    dim3 gC(NPAD / 128, MM / 128);
    out_gemm_mma<<<gC, 256, SMEM_GEMM>>>(b_aff, out);
}

// round 5
// speedup vs baseline: 1.9766x; 1.0847x over previous
#include <cuda_runtime.h>
#include <cuda_bf16.h>
#include <cstdint>

#define BB 128
#define SS 50
#define XX 128
#define HH 256
#define VV 10000
#define MM (BB*SS)     // 6400
#define NPAD 10240     // VV padded to N-tile multiple

// ---------------- device scratch (no allocs allowed in kernel_launch) ------
__device__ float g_xin[MM * HH];                         // input projection
__device__ float g_WT[HH * HH];                          // W_hh transposed: [k][j]
__device__ __align__(16) __nv_bfloat16 g_A2[MM * 512];   // [m][0:256]=hi, [256:512]=lo of h
__device__ __align__(16) __nv_bfloat16 g_B2[(size_t)NPAD * 512]; // same split of W_aff

// ---------------- packed fp32x2 helpers --------------------------------------
__device__ __forceinline__ double dup2(float x) {
    double r; asm("mov.b64 %0, {%1, %1};" : "=d"(r) : "f"(x)); return r;
}
__device__ __forceinline__ double pk2(float lo, float hi) {
    double r; asm("mov.b64 %0, {%1, %2};" : "=d"(r) : "f"(lo), "f"(hi)); return r;
}
__device__ __forceinline__ float2 unpk(double d) {
    float2 f; asm("mov.b64 {%0, %1}, %2;" : "=f"(f.x), "=f"(f.y) : "d"(d)); return f;
}
__device__ __forceinline__ void ffma2(double& acc, double a, double b) {
    asm("fma.rn.f32x2 %0, %1, %2, %0;" : "+d"(acc) : "d"(a), "d"(b));
}
__device__ __forceinline__ double fadd2(double a, double b) {
    double r; asm("add.rn.f32x2 %0, %1, %2;" : "=d"(r) : "d"(a), "d"(b)); return r;
}

// ---------------- mma / smem helpers ------------------------------------------
__device__ __forceinline__ uint32_t smem_u32(const void* p) {
    uint32_t a;
    asm("{ .reg .u64 t; cvta.to.shared.u64 t, %1; cvt.u32.u64 %0, t; }" : "=r"(a) : "l"(p));
    return a;
}
__device__ __forceinline__ void cp_async16(uint32_t dst, const void* src) {
    asm volatile("cp.async.cg.shared.global [%0], [%1], 16;"
                 :: "r"(dst), "l"(src) : "memory");
}
__device__ __forceinline__ void ldsm4(uint32_t r[4], uint32_t addr) {
    asm volatile("ldmatrix.sync.aligned.m8n8.x4.shared.b16 {%0,%1,%2,%3}, [%4];"
                 : "=r"(r[0]), "=r"(r[1]), "=r"(r[2]), "=r"(r[3]) : "r"(addr));
}
__device__ __forceinline__ void mma16816(float c[4], const uint32_t a[4],
                                         uint32_t b0, uint32_t b1) {
    asm volatile(
        "mma.sync.aligned.m16n8k16.row.col.f32.bf16.bf16.f32 "
        "{%0,%1,%2,%3}, {%4,%5,%6,%7}, {%8,%9}, {%0,%1,%2,%3};"
        : "+f"(c[0]), "+f"(c[1]), "+f"(c[2]), "+f"(c[3])
        : "r"(a[0]), "r"(a[1]), "r"(a[2]), "r"(a[3]), "r"(b0), "r"(b1));
}
#define SW128(x) ((x) ^ (((x) >> 3) & 0x70))

__device__ __forceinline__ void store_split(__nv_bfloat16* p, float v) {
    __nv_bfloat16 hi = __float2bfloat16(v);
    p[0]   = hi;
    p[256] = __float2bfloat16(v - __bfloat162float(hi));
}

// ============================================================================
// Kernel A (fused prep):
//   blocks [0, 200):        embedding gather + input projection -> g_xin
//   blocks [200, 2760):     split W_aff -> g_B2 (hi|lo bf16, NPAD rows)
//   blocks [2760, 3016):    transpose W_hh -> g_WT
// ============================================================================
#define NB_EMB 200
#define NB_SPL 2560
#define NB_TRA 256
#define NB_PREP (NB_EMB + NB_SPL + NB_TRA)

__global__ void __launch_bounds__(256)
prep(const int* __restrict__ xraw,
     const float* __restrict__ emb,
     const float* __restrict__ W_ih,
     const float* __restrict__ b_ih,
     const float* __restrict__ b_hh,
     const float* __restrict__ W_hh,
     const float* __restrict__ Wa)
{
    const int bb = blockIdx.x;

    if (bb >= NB_EMB + NB_SPL) {                 // ---- transpose W_hh ----
        int idx = (bb - NB_EMB - NB_SPL) * 256 + threadIdx.x;  // 65536 elems
        int k = idx >> 8, j = idx & 255;
        g_WT[k * HH + j] = W_hh[j * HH + k];
        return;
    }
    if (bb >= NB_EMB) {                          // ---- split W_aff ----
        int idx = (bb - NB_EMB) * 256 + threadIdx.x;   // NPAD * 64
        int n  = idx >> 6;
        int k4 = (idx & 63) << 2;
        float4 w = make_float4(0.f, 0.f, 0.f, 0.f);
        if (n < VV) w = *(const float4*)(Wa + (size_t)n * 256 + k4);
        __nv_bfloat16* p = g_B2 + (size_t)n * 512 + k4;
        __nv_bfloat16 h0 = __float2bfloat16(w.x);
        __nv_bfloat16 h1 = __float2bfloat16(w.y);
        __nv_bfloat16 h2 = __float2bfloat16(w.z);
        __nv_bfloat16 h3 = __float2bfloat16(w.w);
        p[0] = h0; p[1] = h1; p[2] = h2; p[3] = h3;
        p[256] = __float2bfloat16(w.x - __bfloat162float(h0));
        p[257] = __float2bfloat16(w.y - __bfloat162float(h1));
        p[258] = __float2bfloat16(w.z - __bfloat162float(h2));
        p[259] = __float2bfloat16(w.w - __bfloat162float(h3));
        return;
    }

    // ---- embedding + input projection ----
    __shared__ __align__(16) float se[32][XX];

    const bool is64 = ((xraw[1] | xraw[3] | xraw[5] | xraw[7] | xraw[9]) == 0) &&
                      ((xraw[0] | xraw[2] | xraw[4] | xraw[6] | xraw[8]) != 0);

    const int m0 = bb * 32;
    for (int i = threadIdx.x; i < 32 * (XX / 4); i += 256) {
        int r = i >> 5, c = i & 31;
        int m = m0 + r;
        int tok = is64 ? xraw[2 * m] : xraw[m];
        ((float4*)se[r])[c] = ((const float4*)(emb + (long long)tok * XX))[c];
    }
    __syncthreads();

    const int j = threadIdx.x;
    const float bias = b_ih[j] + b_hh[j];
    float acc[32];
#pragma unroll
    for (int r = 0; r < 32; r++) acc[r] = bias;

    const float* wr = W_ih + j * XX;
#pragma unroll 4
    for (int k = 0; k < XX; k += 4) {
        float4 w = *(const float4*)(wr + k);
#pragma unroll
        for (int r = 0; r < 32; r++) {
            float4 e = *(const float4*)&se[r][k];
            acc[r] = fmaf(w.x, e.x, fmaf(w.y, e.y, fmaf(w.z, e.z, fmaf(w.w, e.w, acc[r]))));
        }
    }
#pragma unroll
    for (int r = 0; r < 32; r++)
        g_xin[(m0 + r) * HH + j] = acc[r];
}

// ============================================================================
// Kernel B: RNN scan with COALESCED W reads (g_WT[k][j], lanes j consecutive).
// 32 CTAs x 256 threads; thread j computes output unit j for 4 batch rows.
// 4 accumulator chains (even/odd k) to cover FFMA2 RAW latency.
// ============================================================================
__global__ void __launch_bounds__(256)
rnn_scan()
{
    __shared__ __align__(16) float4 hbuf[2][HH];

    const int j  = threadIdx.x;
    const int b0 = blockIdx.x * 4;

    hbuf[0][j] = make_float4(0.f, 0.f, 0.f, 0.f);
    __syncthreads();

    const float* wt = g_WT + j;
    const float* xin0 = g_xin + (b0 + 0) * SS * HH + j;
    const float* xin1 = g_xin + (b0 + 1) * SS * HH + j;
    const float* xin2 = g_xin + (b0 + 2) * SS * HH + j;
    const float* xin3 = g_xin + (b0 + 3) * SS * HH + j;
    __nv_bfloat16* a0 = g_A2 + (size_t)(b0 + 0) * SS * 512 + j;
    __nv_bfloat16* a1 = g_A2 + (size_t)(b0 + 1) * SS * 512 + j;
    __nv_bfloat16* a2 = g_A2 + (size_t)(b0 + 2) * SS * 512 + j;
    __nv_bfloat16* a3 = g_A2 + (size_t)(b0 + 3) * SS * 512 + j;

    int cur = 0;
    for (int t = 0; t < SS; ++t) {
        double a01 = pk2(xin0[t * HH], xin1[t * HH]);
        double a23 = pk2(xin2[t * HH], xin3[t * HH]);
        double c01 = 0.0, c23 = 0.0;     // bit pattern 0 == packed (0.f, 0.f)

        const double2* hc = (const double2*)hbuf[cur];
#pragma unroll 8
        for (int k = 0; k < HH; k += 2) {
            float w0 = wt[k * HH];
            float w1 = wt[(k + 1) * HH];
            double2 h0 = hc[k];
            double2 h1 = hc[k + 1];
            double wd0 = dup2(w0), wd1 = dup2(w1);
            ffma2(a01, wd0, h0.x); ffma2(a23, wd0, h0.y);
            ffma2(c01, wd1, h1.x); ffma2(c23, wd1, h1.y);
        }

        float2 f01 = unpk(fadd2(a01, c01));
        float2 f23 = unpk(fadd2(a23, c23));
        float h0 = tanhf(f01.x), h1 = tanhf(f01.y);
        float h2 = tanhf(f23.x), h3 = tanhf(f23.y);

        hbuf[cur ^ 1][j] = make_float4(h0, h1, h2, h3);
        store_split(a0 + (size_t)t * 512, h0);
        store_split(a1 + (size_t)t * 512, h1);
        store_split(a2 + (size_t)t * 512, h2);
        store_split(a3 + (size_t)t * 512, h3);

        cur ^= 1;
        __syncthreads();
    }
}

// ============================================================================
// Kernel C: bf16-split output GEMM, mma.sync m16n8k16, 3-stage cp.async
// pipeline with a single barrier per K-chunk.
//   C[m][n] = A_hi.B_hi + A_lo.B_hi + A_hi.B_lo + b_aff[n]
// ============================================================================
#define TILE_BYTES 16384              // 128 rows x 128 bytes (64 bf16)
#define STAGE_BYTES (2 * TILE_BYTES)  // A + B per stage
#define NSTAGE 3
#define SMEM_GEMM (NSTAGE * STAGE_BYTES)   // 98304

__global__ void __launch_bounds__(256, 2)
out_gemm_mma(const float* __restrict__ ba, float* __restrict__ C)
{
    extern __shared__ __align__(1024) char smem[];
    const uint32_t sb = smem_u32(smem);

    const int tid  = threadIdx.x;
    const int wid  = tid >> 5;
    const int lane = tid & 31;
    const int bm   = blockIdx.y * 128;
    const int bn   = blockIdx.x * 128;

    // ---- loader geometry: 4 x 16B per thread per tile ----
    uint32_t t_sw[4];
    const __nv_bfloat16* a_src[4];
    const __nv_bfloat16* b_src[4];
#pragma unroll
    for (int i = 0; i < 4; i++) {
        int idx = i * 256 + tid, row = idx >> 3, c = idx & 7;
        t_sw[i] = SW128(row * 128 + c * 16);
        a_src[i] = g_A2 + (size_t)(bm + row) * 512 + c * 8;
        b_src[i] = g_B2 + (size_t)(bn + row) * 512 + c * 8;
    }

    // ---- per-lane ldmatrix geometry ----
    const int wm0 = (wid >> 1) * 32;
    const int wn0 = (wid & 1) * 64;
    const int a_row  = wm0 + (lane & 7) + ((lane & 8) ? 8 : 0);
    const int a_koff = (lane & 16) ? 16 : 0;
    const int b_row  = wn0 + (lane & 7) + ((lane & 16) ? 8 : 0);
    const int b_koff = (lane & 8) ? 16 : 0;

    float acc[2][8][4];
#pragma unroll
    for (int mt = 0; mt < 2; mt++)
#pragma unroll
        for (int nt = 0; nt < 8; nt++)
#pragma unroll
            for (int q = 0; q < 4; q++) acc[mt][nt][q] = 0.f;

    // seg 0: Ahi.Bhi, 1: Alo.Bhi, 2: Ahi.Blo  (K-chunks of 64)
    auto prefetch = [&](int ch) {
        const int seg = ch >> 2, s = ch & 3;
        const int aoff = ((seg == 1) ? 256 : 0) + s * 64;
        const int boff = ((seg == 2) ? 256 : 0) + s * 64;
        const uint32_t base = sb + (ch % NSTAGE) * STAGE_BYTES;
#pragma unroll
        for (int i = 0; i < 4; i++) cp_async16(base + t_sw[i], a_src[i] + aoff);
#pragma unroll
        for (int i = 0; i < 4; i++) cp_async16(base + TILE_BYTES + t_sw[i], b_src[i] + boff);
        asm volatile("cp.async.commit_group;" ::: "memory");
    };

    prefetch(0);
    prefetch(1);

#pragma unroll 1
    for (int ch = 0; ch < 12; ++ch) {
        if (ch < 11) asm volatile("cp.async.wait_group 1;" ::: "memory");
        else         asm volatile("cp.async.wait_group 0;" ::: "memory");
        __syncthreads();
        // Safe to refill stage (ch+2)%3: all threads are past compute(ch-1),
        // which was the last reader of that stage.
        if (ch + 2 < 12) prefetch(ch + 2);

        const uint32_t Ab = sb + (ch % NSTAGE) * STAGE_BYTES;
        const uint32_t Bb = Ab + TILE_BYTES;

#pragma unroll
        for (int ks = 0; ks < 4; ++ks) {
            const int kb = ks * 32;
            uint32_t a[2][4], b[4][4];
#pragma unroll
            for (int mt = 0; mt < 2; mt++)
                ldsm4(a[mt], Ab + SW128((a_row + mt * 16) * 128 + kb + a_koff));
#pragma unroll
            for (int p = 0; p < 4; p++)
                ldsm4(b[p], Bb + SW128((b_row + p * 16) * 128 + kb + b_koff));
#pragma unroll
            for (int mt = 0; mt < 2; mt++)
#pragma unroll
                for (int p = 0; p < 4; p++) {
                    mma16816(acc[mt][2 * p + 0], a[mt], b[p][0], b[p][1]);
                    mma16816(acc[mt][2 * p + 1], a[mt], b[p][2], b[p][3]);
                }
        }
    }

    // ---- epilogue: direct register-fragment stores with bias ----
    const int lm = lane >> 2;
    const int lq = (lane & 3) * 2;
#pragma unroll
    for (int nt = 0; nt < 8; nt++) {
        const int gcol = bn + wn0 + nt * 8 + lq;
        if (gcol >= VV) continue;
        const float2 bv = *(const float2*)(ba + gcol);
#pragma unroll
        for (int mt = 0; mt < 2; mt++) {
            const int row = bm + wm0 + mt * 16 + lm;
            float* c0 = C + (size_t)row * VV + gcol;
            float2 o0 = make_float2(acc[mt][nt][0] + bv.x, acc[mt][nt][1] + bv.y);
            float2 o1 = make_float2(acc[mt][nt][2] + bv.x, acc[mt][nt][3] + bv.y);
            *(float2*)c0            = o0;
            *(float2*)(c0 + 8 * VV) = o1;
        }
    }
}

// ============================================================================
extern "C" void kernel_launch(void* const* d_in, const int* in_sizes, int n_in,
                              void* d_out, int out_size)
{
    const int*   x     = (const int*)  d_in[0];
    const float* emb   = (const float*)d_in[1];
    const float* W_ih  = (const float*)d_in[2];
    const float* W_hh  = (const float*)d_in[3];
    const float* b_ih  = (const float*)d_in[4];
    const float* b_hh  = (const float*)d_in[5];
    const float* W_aff = (const float*)d_in[6];
    const float* b_aff = (const float*)d_in[7];
    float* out = (float*)d_out;

    cudaFuncSetAttribute(out_gemm_mma, cudaFuncAttributeMaxDynamicSharedMemorySize, SMEM_GEMM);

    prep<<<NB_PREP, 256>>>(x, emb, W_ih, b_ih, b_hh, W_hh, W_aff);
    rnn_scan<<<BB / 4, 256>>>();
    dim3 gC(NPAD / 128, MM / 128);
    out_gemm_mma<<<gC, 256, SMEM_GEMM>>>(b_aff, out);
}

// round 7
// speedup vs baseline: 3.2897x; 1.6643x over previous
#include <cuda_runtime.h>
#include <cuda_bf16.h>
#include <cstdint>

#define BB 128
#define SS 50
#define XX 128
#define HH 256
#define VV 10000
#define MM (BB*SS)     // 6400
#define NPAD 10240     // VV padded to N-tile multiple

// ---------------- device scratch (no allocs allowed in kernel_launch) ------
__device__ float g_xin[MM * HH];                         // input projection
__device__ float g_WT[HH * HH];                          // W_hh transposed: [k][j]
__device__ __align__(16) __nv_bfloat16 g_A2[MM * 512];   // [m][0:256]=hi, [256:512]=lo of h
__device__ __align__(16) __nv_bfloat16 g_B2[(size_t)NPAD * 512]; // same split of W_aff

// ---------------- packed fp32x2 helpers --------------------------------------
__device__ __forceinline__ double dup2(float x) {
    double r; asm("mov.b64 %0, {%1, %1};" : "=d"(r) : "f"(x)); return r;
}
__device__ __forceinline__ double pk2(float lo, float hi) {
    double r; asm("mov.b64 %0, {%1, %2};" : "=d"(r) : "f"(lo), "f"(hi)); return r;
}
__device__ __forceinline__ float2 unpk(double d) {
    float2 f; asm("mov.b64 {%0, %1}, %2;" : "=f"(f.x), "=f"(f.y) : "d"(d)); return f;
}
__device__ __forceinline__ void ffma2(double& acc, double a, double b) {
    asm("fma.rn.f32x2 %0, %1, %2, %0;" : "+d"(acc) : "d"(a), "d"(b));
}
__device__ __forceinline__ double fadd2(double a, double b) {
    double r; asm("add.rn.f32x2 %0, %1, %2;" : "=d"(r) : "d"(a), "d"(b)); return r;
}

// ---------------- mma / smem helpers ------------------------------------------
__device__ __forceinline__ uint32_t smem_u32(const void* p) {
    uint32_t a;
    asm("{ .reg .u64 t; cvta.to.shared.u64 t, %1; cvt.u32.u64 %0, t; }" : "=r"(a) : "l"(p));
    return a;
}
__device__ __forceinline__ void cp_async16(uint32_t dst, const void* src) {
    asm volatile("cp.async.cg.shared.global [%0], [%1], 16;"
                 :: "r"(dst), "l"(src) : "memory");
}
__device__ __forceinline__ void ldsm4(uint32_t r[4], uint32_t addr) {
    asm volatile("ldmatrix.sync.aligned.m8n8.x4.shared.b16 {%0,%1,%2,%3}, [%4];"
                 : "=r"(r[0]), "=r"(r[1]), "=r"(r[2]), "=r"(r[3]) : "r"(addr));
}
__device__ __forceinline__ void mma16816(float c[4], const uint32_t a[4],
                                         uint32_t b0, uint32_t b1) {
    asm volatile(
        "mma.sync.aligned.m16n8k16.row.col.f32.bf16.bf16.f32 "
        "{%0,%1,%2,%3}, {%4,%5,%6,%7}, {%8,%9}, {%0,%1,%2,%3};"
        : "+f"(c[0]), "+f"(c[1]), "+f"(c[2]), "+f"(c[3])
        : "r"(a[0]), "r"(a[1]), "r"(a[2]), "r"(a[3]), "r"(b0), "r"(b1));
}
#define SW128(x) ((x) ^ (((x) >> 3) & 0x70))

__device__ __forceinline__ void store_split(__nv_bfloat16* p, float v) {
    __nv_bfloat16 hi = __float2bfloat16(v);
    p[0]   = hi;
    p[256] = __float2bfloat16(v - __bfloat162float(hi));
}

// ============================================================================
// Kernel A (fused prep): embed+proj | split W_aff | transpose W_hh
// ============================================================================
#define NB_EMB 200
#define NB_SPL 2560
#define NB_TRA 256
#define NB_PREP (NB_EMB + NB_SPL + NB_TRA)

__global__ void __launch_bounds__(256)
prep(const int* __restrict__ xraw,
     const float* __restrict__ emb,
     const float* __restrict__ W_ih,
     const float* __restrict__ b_ih,
     const float* __restrict__ b_hh,
     const float* __restrict__ W_hh,
     const float* __restrict__ Wa)
{
    const int bb = blockIdx.x;

    if (bb >= NB_EMB + NB_SPL) {                 // ---- transpose W_hh ----
        int idx = (bb - NB_EMB - NB_SPL) * 256 + threadIdx.x;  // 65536 elems
        int k = idx >> 8, j = idx & 255;
        g_WT[k * HH + j] = W_hh[j * HH + k];
        return;
    }
    if (bb >= NB_EMB) {                          // ---- split W_aff ----
        int idx = (bb - NB_EMB) * 256 + threadIdx.x;   // NPAD * 64
        int n  = idx >> 6;
        int k4 = (idx & 63) << 2;
        float4 w = make_float4(0.f, 0.f, 0.f, 0.f);
        if (n < VV) w = *(const float4*)(Wa + (size_t)n * 256 + k4);
        __nv_bfloat16* p = g_B2 + (size_t)n * 512 + k4;
        __nv_bfloat16 h0 = __float2bfloat16(w.x);
        __nv_bfloat16 h1 = __float2bfloat16(w.y);
        __nv_bfloat16 h2 = __float2bfloat16(w.z);
        __nv_bfloat16 h3 = __float2bfloat16(w.w);
        p[0] = h0; p[1] = h1; p[2] = h2; p[3] = h3;
        p[256] = __float2bfloat16(w.x - __bfloat162float(h0));
        p[257] = __float2bfloat16(w.y - __bfloat162float(h1));
        p[258] = __float2bfloat16(w.z - __bfloat162float(h2));
        p[259] = __float2bfloat16(w.w - __bfloat162float(h3));
        return;
    }

    // ---- embedding + input projection ----
    __shared__ __align__(16) float se[32][XX];

    const bool is64 = ((xraw[1] | xraw[3] | xraw[5] | xraw[7] | xraw[9]) == 0) &&
                      ((xraw[0] | xraw[2] | xraw[4] | xraw[6] | xraw[8]) != 0);

    const int m0 = bb * 32;
    for (int i = threadIdx.x; i < 32 * (XX / 4); i += 256) {
        int r = i >> 5, c = i & 31;
        int m = m0 + r;
        int tok = is64 ? xraw[2 * m] : xraw[m];
        ((float4*)se[r])[c] = ((const float4*)(emb + (long long)tok * XX))[c];
    }
    __syncthreads();

    const int j = threadIdx.x;
    const float bias = b_ih[j] + b_hh[j];
    float acc[32];
#pragma unroll
    for (int r = 0; r < 32; r++) acc[r] = bias;

    const float* wr = W_ih + j * XX;
#pragma unroll 4
    for (int k = 0; k < XX; k += 4) {
        float4 w = *(const float4*)(wr + k);
#pragma unroll
        for (int r = 0; r < 32; r++) {
            float4 e = *(const float4*)&se[r][k];
            acc[r] = fmaf(w.x, e.x, fmaf(w.y, e.y, fmaf(w.z, e.z, fmaf(w.w, e.w, acc[r]))));
        }
    }
#pragma unroll
    for (int r = 0; r < 32; r++)
        g_xin[(m0 + r) * HH + j] = acc[r];
}

// ============================================================================
// Kernel B: RNN scan, 2-CTA clusters, W half resident in SMEM, DSMEM h-exchange
//   cluster c (of 32): batch rows b0 = c*4 .. c*4+3
//   rank r in {0,1}: owns output columns jg = r*128 .. r*128+127
//   thread (rp = tid>>7, jl = tid&127): column jg = r*128+jl, rows (2rp, 2rp+1)
// SMEM: wsp[k2][jl] = (W[jg][2k2], W[jg][2k2+1])  -> 128 KB
//       hb  [buf][rp][col] float2 = (h[col] row 2rp, row 2rp+1)
// ============================================================================
#define RNN_W_F2   (128 * 128)                 // float2 count for W half
#define RNN_HB_F2  (2 * 2 * 256)               // [buf][rp][col]
#define RNN_SMEM   ((RNN_W_F2 + RNN_HB_F2) * 8)   // 139264 bytes

__global__ void __launch_bounds__(256) __cluster_dims__(2, 1, 1)
rnn_scan()
{
    extern __shared__ __align__(16) float2 sm[];
    float2* wsp = sm;                  // [k2*128 + jl]
    float2* hb  = sm + RNN_W_F2;       // [(buf*2 + rp)*256 + col]
    const uint32_t hb_addr = smem_u32(hb);

    const int tid  = threadIdx.x;
    const int rp   = tid >> 7;
    const int jl   = tid & 127;
    const uint32_t rank = blockIdx.x & 1;
    const int jg   = rank * 128 + jl;
    const int b0   = (blockIdx.x >> 1) * 4;

    // fill W half: wsp[k2][jl] = (WT[2k2][jg], WT[2k2+1][jg])
    for (int i = tid; i < RNN_W_F2; i += 256) {
        int k2 = i >> 7, j = i & 127;
        int jgl = rank * 128 + j;
        wsp[i] = make_float2(g_WT[(2 * k2) * HH + jgl],
                             g_WT[(2 * k2 + 1) * HH + jgl]);
    }
    // zero h buffer 0
    for (int i = tid; i < 2 * 256; i += 256) hb[i] = make_float2(0.f, 0.f);

    asm volatile("barrier.cluster.arrive.aligned;" ::: "memory");
    asm volatile("barrier.cluster.wait.aligned;" ::: "memory");

    const int r0 = b0 + 2 * rp;
    const float* x0p = g_xin + (size_t)r0 * SS * HH + jg;
    const float* x1p = g_xin + (size_t)(r0 + 1) * SS * HH + jg;
    __nv_bfloat16* a0p = g_A2 + (size_t)r0 * SS * 512 + jg;
    __nv_bfloat16* a1p = g_A2 + (size_t)(r0 + 1) * SS * 512 + jg;

    const float2* wp = wsp + jl;
    const uint32_t peer = rank ^ 1;

    int cur = 0;
    for (int t = 0; t < SS; ++t) {
        double acc_e = pk2(x0p[(size_t)t * HH], x1p[(size_t)t * HH]);
        double acc_o = 0.0;

        const double2* hc = (const double2*)(hb + (cur * 2 + rp) * 256);
#pragma unroll 8
        for (int k2 = 0; k2 < 128; ++k2) {
            float2 wv  = wp[k2 * 128];
            double2 h2 = hc[k2];
            ffma2(acc_e, dup2(wv.x), h2.x);
            ffma2(acc_o, dup2(wv.y), h2.y);
        }

        float2 f = unpk(fadd2(acc_e, acc_o));
        float h0 = tanhf(f.x), h1 = tanhf(f.y);

        const int nxt = cur ^ 1;
        const long long hp = __double_as_longlong(pk2(h0, h1));
        uint32_t loc = hb_addr + (uint32_t)(((nxt * 2 + rp) * 256 + jg) * 8);
        asm volatile("st.shared.b64 [%0], %1;" :: "r"(loc), "l"(hp) : "memory");
        asm volatile(
            "{\n\t.reg .b32 ra;\n\t"
            "mapa.shared::cluster.u32 ra, %0, %1;\n\t"
            "st.shared::cluster.b64 [ra], %2;\n\t}"
            :: "r"(loc), "r"(peer), "l"(hp) : "memory");

        store_split(a0p + (size_t)t * 512, h0);
        store_split(a1p + (size_t)t * 512, h1);

        asm volatile("barrier.cluster.arrive.aligned;" ::: "memory");
        asm volatile("barrier.cluster.wait.aligned;" ::: "memory");
        cur = nxt;
    }
}

// ============================================================================
// Kernel C: bf16-split output GEMM, mma.sync m16n8k16, 3-stage cp.async
// ============================================================================
#define TILE_BYTES 16384              // 128 rows x 128 bytes (64 bf16)
#define STAGE_BYTES (2 * TILE_BYTES)
#define NSTAGE 3
#define SMEM_GEMM (NSTAGE * STAGE_BYTES)   // 98304

__global__ void __launch_bounds__(256, 2)
out_gemm_mma(const float* __restrict__ ba, float* __restrict__ C)
{
    extern __shared__ __align__(1024) char smem[];
    const uint32_t sb = smem_u32(smem);

    const int tid  = threadIdx.x;
    const int wid  = tid >> 5;
    const int lane = tid & 31;
    const int bm   = blockIdx.y * 128;
    const int bn   = blockIdx.x * 128;

    uint32_t t_sw[4];
    const __nv_bfloat16* a_src[4];
    const __nv_bfloat16* b_src[4];
#pragma unroll
    for (int i = 0; i < 4; i++) {
        int idx = i * 256 + tid, row = idx >> 3, c = idx & 7;
        t_sw[i] = SW128(row * 128 + c * 16);
        a_src[i] = g_A2 + (size_t)(bm + row) * 512 + c * 8;
        b_src[i] = g_B2 + (size_t)(bn + row) * 512 + c * 8;
    }

    const int wm0 = (wid >> 1) * 32;
    const int wn0 = (wid & 1) * 64;
    const int a_row  = wm0 + (lane & 7) + ((lane & 8) ? 8 : 0);
    const int a_koff = (lane & 16) ? 16 : 0;
    const int b_row  = wn0 + (lane & 7) + ((lane & 16) ? 8 : 0);
    const int b_koff = (lane & 8) ? 16 : 0;

    float acc[2][8][4];
#pragma unroll
    for (int mt = 0; mt < 2; mt++)
#pragma unroll
        for (int nt = 0; nt < 8; nt++)
#pragma unroll
            for (int q = 0; q < 4; q++) acc[mt][nt][q] = 0.f;

    auto prefetch = [&](int ch) {
        const int seg = ch >> 2, s = ch & 3;
        const int aoff = ((seg == 1) ? 256 : 0) + s * 64;
        const int boff = ((seg == 2) ? 256 : 0) + s * 64;
        const uint32_t base = sb + (ch % NSTAGE) * STAGE_BYTES;
#pragma unroll
        for (int i = 0; i < 4; i++) cp_async16(base + t_sw[i], a_src[i] + aoff);
#pragma unroll
        for (int i = 0; i < 4; i++) cp_async16(base + TILE_BYTES + t_sw[i], b_src[i] + boff);
        asm volatile("cp.async.commit_group;" ::: "memory");
    };

    prefetch(0);
    prefetch(1);

#pragma unroll 1
    for (int ch = 0; ch < 12; ++ch) {
        if (ch < 11) asm volatile("cp.async.wait_group 1;" ::: "memory");
        else         asm volatile("cp.async.wait_group 0;" ::: "memory");
        __syncthreads();
        if (ch + 2 < 12) prefetch(ch + 2);

        const uint32_t Ab = sb + (ch % NSTAGE) * STAGE_BYTES;
        const uint32_t Bb = Ab + TILE_BYTES;

#pragma unroll
        for (int ks = 0; ks < 4; ++ks) {
            const int kb = ks * 32;
            uint32_t a[2][4], b[4][4];
#pragma unroll
            for (int mt = 0; mt < 2; mt++)
                ldsm4(a[mt], Ab + SW128((a_row + mt * 16) * 128 + kb + a_koff));
#pragma unroll
            for (int p = 0; p < 4; p++)
                ldsm4(b[p], Bb + SW128((b_row + p * 16) * 128 + kb + b_koff));
#pragma unroll
            for (int mt = 0; mt < 2; mt++)
#pragma unroll
                for (int p = 0; p < 4; p++) {
                    mma16816(acc[mt][2 * p + 0], a[mt], b[p][0], b[p][1]);
                    mma16816(acc[mt][2 * p + 1], a[mt], b[p][2], b[p][3]);
                }
        }
    }

    const int lm = lane >> 2;
    const int lq = (lane & 3) * 2;
#pragma unroll
    for (int nt = 0; nt < 8; nt++) {
        const int gcol = bn + wn0 + nt * 8 + lq;
        if (gcol >= VV) continue;
        const float2 bv = *(const float2*)(ba + gcol);
#pragma unroll
        for (int mt = 0; mt < 2; mt++) {
            const int row = bm + wm0 + mt * 16 + lm;
            float* c0 = C + (size_t)row * VV + gcol;
            float2 o0 = make_float2(acc[mt][nt][0] + bv.x, acc[mt][nt][1] + bv.y);
            float2 o1 = make_float2(acc[mt][nt][2] + bv.x, acc[mt][nt][3] + bv.y);
            *(float2*)c0            = o0;
            *(float2*)(c0 + 8 * VV) = o1;
        }
    }
}

// ============================================================================
extern "C" void kernel_launch(void* const* d_in, const int* in_sizes, int n_in,
                              void* d_out, int out_size)
{
    const int*   x     = (const int*)  d_in[0];
    const float* emb   = (const float*)d_in[1];
    const float* W_ih  = (const float*)d_in[2];
    const float* W_hh  = (const float*)d_in[3];
    const float* b_ih  = (const float*)d_in[4];
    const float* b_hh  = (const float*)d_in[5];
    const float* W_aff = (const float*)d_in[6];
    const float* b_aff = (const float*)d_in[7];
    float* out = (float*)d_out;

    cudaFuncSetAttribute(out_gemm_mma, cudaFuncAttributeMaxDynamicSharedMemorySize, SMEM_GEMM);
    cudaFuncSetAttribute(rnn_scan,     cudaFuncAttributeMaxDynamicSharedMemorySize, RNN_SMEM);

    prep<<<NB_PREP, 256>>>(x, emb, W_ih, b_ih, b_hh, W_hh, W_aff);
    rnn_scan<<<64, 256, RNN_SMEM>>>();
    dim3 gC(NPAD / 128, MM / 128);
    out_gemm_mma<<<gC, 256, SMEM_GEMM>>>(b_aff, out);
}

// round 8
// speedup vs baseline: 3.4005x; 1.0337x over previous
#include <cuda_runtime.h>
#include <cuda_bf16.h>
#include <cstdint>

#define BB 128
#define SS 50
#define XX 128
#define HH 256
#define VV 10000
#define MM (BB*SS)     // 6400
#define NPAD 10240     // VV padded to N-tile multiple

// ---------------- device scratch (no allocs allowed in kernel_launch) ------
__device__ float g_xin[MM * HH];                         // input projection [b][t][j]
__device__ float g_WT[HH * HH];                          // W_hh transposed: [k][j]
// t-MAJOR: row m = t*128 + b ; [m][0:256]=hi, [256:512]=lo
__device__ __align__(16) __nv_bfloat16 g_A2[MM * 512];
__device__ __align__(16) __nv_bfloat16 g_B2[(size_t)NPAD * 512]; // split of W_aff
__device__ int g_prog[SS];                               // per-step producer arrivals

// ---------------- packed fp32x2 helpers --------------------------------------
__device__ __forceinline__ double dup2(float x) {
    double r; asm("mov.b64 %0, {%1, %1};" : "=d"(r) : "f"(x)); return r;
}
__device__ __forceinline__ double pk2(float lo, float hi) {
    double r; asm("mov.b64 %0, {%1, %2};" : "=d"(r) : "f"(lo), "f"(hi)); return r;
}
__device__ __forceinline__ float2 unpk(double d) {
    float2 f; asm("mov.b64 {%0, %1}, %2;" : "=f"(f.x), "=f"(f.y) : "d"(d)); return f;
}
__device__ __forceinline__ void ffma2(double& acc, double a, double b) {
    asm("fma.rn.f32x2 %0, %1, %2, %0;" : "+d"(acc) : "d"(a), "d"(b));
}
__device__ __forceinline__ double fadd2(double a, double b) {
    double r; asm("add.rn.f32x2 %0, %1, %2;" : "=d"(r) : "d"(a), "d"(b)); return r;
}

// ---------------- mma / smem helpers ------------------------------------------
__device__ __forceinline__ uint32_t smem_u32(const void* p) {
    uint32_t a;
    asm("{ .reg .u64 t; cvta.to.shared.u64 t, %1; cvt.u32.u64 %0, t; }" : "=r"(a) : "l"(p));
    return a;
}
__device__ __forceinline__ void cp_async16(uint32_t dst, const void* src) {
    asm volatile("cp.async.cg.shared.global [%0], [%1], 16;"
                 :: "r"(dst), "l"(src) : "memory");
}
__device__ __forceinline__ void ldsm4(uint32_t r[4], uint32_t addr) {
    asm volatile("ldmatrix.sync.aligned.m8n8.x4.shared.b16 {%0,%1,%2,%3}, [%4];"
                 : "=r"(r[0]), "=r"(r[1]), "=r"(r[2]), "=r"(r[3]) : "r"(addr));
}
__device__ __forceinline__ void mma16816(float c[4], const uint32_t a[4],
                                         uint32_t b0, uint32_t b1) {
    asm volatile(
        "mma.sync.aligned.m16n8k16.row.col.f32.bf16.bf16.f32 "
        "{%0,%1,%2,%3}, {%4,%5,%6,%7}, {%8,%9}, {%0,%1,%2,%3};"
        : "+f"(c[0]), "+f"(c[1]), "+f"(c[2]), "+f"(c[3])
        : "r"(a[0]), "r"(a[1]), "r"(a[2]), "r"(a[3]), "r"(b0), "r"(b1));
}
__device__ __forceinline__ int ld_acq(const int* p) {
    int v; asm volatile("ld.acquire.gpu.global.b32 %0, [%1];" : "=r"(v) : "l"(p)); return v;
}
#define SW128(x) ((x) ^ (((x) >> 3) & 0x70))

__device__ __forceinline__ void store_split(__nv_bfloat16* p, float v) {
    __nv_bfloat16 hi = __float2bfloat16(v);
    p[0]   = hi;
    p[256] = __float2bfloat16(v - __bfloat162float(hi));
}

// ============================================================================
// Kernel A (fused prep): embed+proj | split W_aff | transpose W_hh | zero prog
// ============================================================================
#define NB_EMB 200
#define NB_SPL 2560
#define NB_TRA 256
#define NB_PREP (NB_EMB + NB_SPL + NB_TRA)

__global__ void __launch_bounds__(256)
prep(const int* __restrict__ xraw,
     const float* __restrict__ emb,
     const float* __restrict__ W_ih,
     const float* __restrict__ b_ih,
     const float* __restrict__ b_hh,
     const float* __restrict__ W_hh,
     const float* __restrict__ Wa)
{
    const int bb = blockIdx.x;

    if (bb >= NB_EMB + NB_SPL) {                 // ---- transpose W_hh ----
        int idx = (bb - NB_EMB - NB_SPL) * 256 + threadIdx.x;  // 65536 elems
        int k = idx >> 8, j = idx & 255;
        g_WT[k * HH + j] = W_hh[j * HH + k];
        return;
    }
    if (bb >= NB_EMB) {                          // ---- split W_aff ----
        int idx = (bb - NB_EMB) * 256 + threadIdx.x;   // NPAD * 64
        int n  = idx >> 6;
        int k4 = (idx & 63) << 2;
        float4 w = make_float4(0.f, 0.f, 0.f, 0.f);
        if (n < VV) w = *(const float4*)(Wa + (size_t)n * 256 + k4);
        __nv_bfloat16* p = g_B2 + (size_t)n * 512 + k4;
        __nv_bfloat16 h0 = __float2bfloat16(w.x);
        __nv_bfloat16 h1 = __float2bfloat16(w.y);
        __nv_bfloat16 h2 = __float2bfloat16(w.z);
        __nv_bfloat16 h3 = __float2bfloat16(w.w);
        p[0] = h0; p[1] = h1; p[2] = h2; p[3] = h3;
        p[256] = __float2bfloat16(w.x - __bfloat162float(h0));
        p[257] = __float2bfloat16(w.y - __bfloat162float(h1));
        p[258] = __float2bfloat16(w.z - __bfloat162float(h2));
        p[259] = __float2bfloat16(w.w - __bfloat162float(h3));
        return;
    }

    // ---- embedding + input projection ----
    if (bb == 0 && threadIdx.x < SS) g_prog[threadIdx.x] = 0;   // reset progress

    __shared__ __align__(16) float se[32][XX];

    const bool is64 = ((xraw[1] | xraw[3] | xraw[5] | xraw[7] | xraw[9]) == 0) &&
                      ((xraw[0] | xraw[2] | xraw[4] | xraw[6] | xraw[8]) != 0);

    const int m0 = bb * 32;
    for (int i = threadIdx.x; i < 32 * (XX / 4); i += 256) {
        int r = i >> 5, c = i & 31;
        int m = m0 + r;
        int tok = is64 ? xraw[2 * m] : xraw[m];
        ((float4*)se[r])[c] = ((const float4*)(emb + (long long)tok * XX))[c];
    }
    __syncthreads();

    const int j = threadIdx.x;
    const float bias = b_ih[j] + b_hh[j];
    float acc[32];
#pragma unroll
    for (int r = 0; r < 32; r++) acc[r] = bias;

    const float* wr = W_ih + j * XX;
#pragma unroll 4
    for (int k = 0; k < XX; k += 4) {
        float4 w = *(const float4*)(wr + k);
#pragma unroll
        for (int r = 0; r < 32; r++) {
            float4 e = *(const float4*)&se[r][k];
            acc[r] = fmaf(w.x, e.x, fmaf(w.y, e.y, fmaf(w.z, e.z, fmaf(w.w, e.w, acc[r]))));
        }
    }
#pragma unroll
    for (int r = 0; r < 32; r++)
        g_xin[(m0 + r) * HH + j] = acc[r];
}

// ============================================================================
// FUSED kernel: rnn producers (bids 0..63) + gemm consumers (bids 64..4063)
// Cluster dims (2,1,1). Unified dynamic smem = max(rnn, gemm) = 139264 B.
// ============================================================================
#define RNN_W_F2   (128 * 128)
#define RNN_HB_F2  (2 * 2 * 256)
#define RNN_SMEM   ((RNN_W_F2 + RNN_HB_F2) * 8)   // 139264

#define TILE_BYTES 16384
#define STAGE_BYTES (2 * TILE_BYTES)
#define NSTAGE 3
#define NB_RNN 64
#define NT_N   (NPAD / 128)            // 80 n-tiles per timestep
#define NB_FUSED (NB_RNN + SS * NT_N)  // 64 + 4000 = 4064

__global__ void __launch_bounds__(256, 1) __cluster_dims__(2, 1, 1)
fused_rnn_gemm(const float* __restrict__ ba, float* __restrict__ C)
{
    extern __shared__ __align__(1024) char smem[];
    const int bid = blockIdx.x;
    const int tid = threadIdx.x;

    if (bid < NB_RNN) {
        // ==================== RNN producer (proven R7 code, t-major store) ===
        float2* sm  = (float2*)smem;
        float2* wsp = sm;                  // [k2*128 + jl]
        float2* hb  = sm + RNN_W_F2;       // [(buf*2 + rp)*256 + col]
        const uint32_t hb_addr = smem_u32(hb);

        const int rp   = tid >> 7;
        const int jl   = tid & 127;
        const uint32_t rank = bid & 1;
        const int jg   = rank * 128 + jl;
        const int b0   = (bid >> 1) * 4;

        for (int i = tid; i < RNN_W_F2; i += 256) {
            int k2 = i >> 7, j = i & 127;
            int jgl = rank * 128 + j;
            wsp[i] = make_float2(g_WT[(2 * k2) * HH + jgl],
                                 g_WT[(2 * k2 + 1) * HH + jgl]);
        }
        for (int i = tid; i < 2 * 256; i += 256) hb[i] = make_float2(0.f, 0.f);

        asm volatile("barrier.cluster.arrive.aligned;" ::: "memory");
        asm volatile("barrier.cluster.wait.aligned;" ::: "memory");

        const int r0 = b0 + 2 * rp;
        const float* x0p = g_xin + (size_t)r0 * SS * HH + jg;
        const float* x1p = g_xin + (size_t)(r0 + 1) * SS * HH + jg;
        // t-major A2: row m = t*BB + b
        __nv_bfloat16* a0p = g_A2 + (size_t)r0 * 512 + jg;         // + t*BB*512
        __nv_bfloat16* a1p = g_A2 + (size_t)(r0 + 1) * 512 + jg;

        const float2* wp = wsp + jl;
        const uint32_t peer = rank ^ 1;

        int cur = 0;
        for (int t = 0; t < SS; ++t) {
            double acc_e = pk2(x0p[(size_t)t * HH], x1p[(size_t)t * HH]);
            double acc_o = 0.0;

            const double2* hc = (const double2*)(hb + (cur * 2 + rp) * 256);
#pragma unroll 8
            for (int k2 = 0; k2 < 128; ++k2) {
                float2 wv  = wp[k2 * 128];
                double2 h2 = hc[k2];
                ffma2(acc_e, dup2(wv.x), h2.x);
                ffma2(acc_o, dup2(wv.y), h2.y);
            }

            float2 f = unpk(fadd2(acc_e, acc_o));
            float h0 = tanhf(f.x), h1 = tanhf(f.y);

            const int nxt = cur ^ 1;
            const long long hp = __double_as_longlong(pk2(h0, h1));
            uint32_t loc = hb_addr + (uint32_t)(((nxt * 2 + rp) * 256 + jg) * 8);
            asm volatile("st.shared.b64 [%0], %1;" :: "r"(loc), "l"(hp) : "memory");
            asm volatile(
                "{\n\t.reg .b32 ra;\n\t"
                "mapa.shared::cluster.u32 ra, %0, %1;\n\t"
                "st.shared::cluster.b64 [ra], %2;\n\t}"
                :: "r"(loc), "r"(peer), "l"(hp) : "memory");

            store_split(a0p + (size_t)t * (BB * 512), h0);
            store_split(a1p + (size_t)t * (BB * 512), h1);
            __threadfence();   // make A2 stores visible device-wide before signal

            asm volatile("barrier.cluster.arrive.aligned;" ::: "memory");
            asm volatile("barrier.cluster.wait.aligned;" ::: "memory");
            if (tid == 0) atomicAdd(&g_prog[t], 1);
            cur = nxt;
        }
        return;
    }

    // ======================= GEMM consumer ==================================
    const int gid = bid - NB_RNN;
    const int tT  = gid / NT_N;            // timestep tile (M-tile)
    const int bn  = (gid % NT_N) * 128;
    const int bm  = tT * 128;

    // wait for all 64 producers of step tT
    if (tid == 0) {
        while (ld_acq(&g_prog[tT]) < NB_RNN) __nanosleep(256);
    }
    __syncthreads();

    const uint32_t sb = smem_u32(smem);
    const int wid  = tid >> 5;
    const int lane = tid & 31;

    uint32_t t_sw[4];
    const __nv_bfloat16* a_src[4];
    const __nv_bfloat16* b_src[4];
#pragma unroll
    for (int i = 0; i < 4; i++) {
        int idx = i * 256 + tid, row = idx >> 3, c = idx & 7;
        t_sw[i] = SW128(row * 128 + c * 16);
        a_src[i] = g_A2 + (size_t)(bm + row) * 512 + c * 8;
        b_src[i] = g_B2 + (size_t)(bn + row) * 512 + c * 8;
    }

    const int wm0 = (wid >> 1) * 32;
    const int wn0 = (wid & 1) * 64;
    const int a_row  = wm0 + (lane & 7) + ((lane & 8) ? 8 : 0);
    const int a_koff = (lane & 16) ? 16 : 0;
    const int b_row  = wn0 + (lane & 7) + ((lane & 16) ? 8 : 0);
    const int b_koff = (lane & 8) ? 16 : 0;

    float acc[2][8][4];
#pragma unroll
    for (int mt = 0; mt < 2; mt++)
#pragma unroll
        for (int nt = 0; nt < 8; nt++)
#pragma unroll
            for (int q = 0; q < 4; q++) acc[mt][nt][q] = 0.f;

    auto prefetch = [&](int ch) {
        const int seg = ch >> 2, s = ch & 3;
        const int aoff = ((seg == 1) ? 256 : 0) + s * 64;
        const int boff = ((seg == 2) ? 256 : 0) + s * 64;
        const uint32_t base = sb + (ch % NSTAGE) * STAGE_BYTES;
#pragma unroll
        for (int i = 0; i < 4; i++) cp_async16(base + t_sw[i], a_src[i] + aoff);
#pragma unroll
        for (int i = 0; i < 4; i++) cp_async16(base + TILE_BYTES + t_sw[i], b_src[i] + boff);
        asm volatile("cp.async.commit_group;" ::: "memory");
    };

    prefetch(0);
    prefetch(1);

#pragma unroll 1
    for (int ch = 0; ch < 12; ++ch) {
        if (ch < 11) asm volatile("cp.async.wait_group 1;" ::: "memory");
        else         asm volatile("cp.async.wait_group 0;" ::: "memory");
        __syncthreads();
        if (ch + 2 < 12) prefetch(ch + 2);

        const uint32_t Ab = sb + (ch % NSTAGE) * STAGE_BYTES;
        const uint32_t Bb = Ab + TILE_BYTES;

#pragma unroll
        for (int ks = 0; ks < 4; ++ks) {
            const int kb = ks * 32;
            uint32_t a[2][4], b[4][4];
#pragma unroll
            for (int mt = 0; mt < 2; mt++)
                ldsm4(a[mt], Ab + SW128((a_row + mt * 16) * 128 + kb + a_koff));
#pragma unroll
            for (int p = 0; p < 4; p++)
                ldsm4(b[p], Bb + SW128((b_row + p * 16) * 128 + kb + b_koff));
#pragma unroll
            for (int mt = 0; mt < 2; mt++)
#pragma unroll
                for (int p = 0; p < 4; p++) {
                    mma16816(acc[mt][2 * p + 0], a[mt], b[p][0], b[p][1]);
                    mma16816(acc[mt][2 * p + 1], a[mt], b[p][2], b[p][3]);
                }
        }
    }

    // epilogue: C row for tile-local row b is m_orig = b*SS + tT
    const int lm = lane >> 2;
    const int lq = (lane & 3) * 2;
#pragma unroll
    for (int nt = 0; nt < 8; nt++) {
        const int gcol = bn + wn0 + nt * 8 + lq;
        if (gcol >= VV) continue;
        const float2 bv = *(const float2*)(ba + gcol);
#pragma unroll
        for (int mt = 0; mt < 2; mt++) {
            const int brow = wm0 + mt * 16 + lm;             // batch index
            float* c0 = C + ((size_t)brow * SS + tT) * VV + gcol;
            float2 o0 = make_float2(acc[mt][nt][0] + bv.x, acc[mt][nt][1] + bv.y);
            float2 o1 = make_float2(acc[mt][nt][2] + bv.x, acc[mt][nt][3] + bv.y);
            *(float2*)c0                      = o0;
            *(float2*)(c0 + (size_t)8 * SS * VV) = o1;       // brow+8
        }
    }
}

// ============================================================================
extern "C" void kernel_launch(void* const* d_in, const int* in_sizes, int n_in,
                              void* d_out, int out_size)
{
    const int*   x     = (const int*)  d_in[0];
    const float* emb   = (const float*)d_in[1];
    const float* W_ih  = (const float*)d_in[2];
    const float* W_hh  = (const float*)d_in[3];
    const float* b_ih  = (const float*)d_in[4];
    const float* b_hh  = (const float*)d_in[5];
    const float* W_aff = (const float*)d_in[6];
    const float* b_aff = (const float*)d_in[7];
    float* out = (float*)d_out;

    cudaFuncSetAttribute(fused_rnn_gemm, cudaFuncAttributeMaxDynamicSharedMemorySize, RNN_SMEM);

    prep<<<NB_PREP, 256>>>(x, emb, W_ih, b_ih, b_hh, W_hh, W_aff);
    fused_rnn_gemm<<<NB_FUSED, 256, RNN_SMEM>>>(b_aff, out);
}

// round 9
// speedup vs baseline: 3.9175x; 1.1520x over previous
#include <cuda_runtime.h>
#include <cuda_bf16.h>
#include <cstdint>

#define BB 128
#define SS 50
#define XX 128
#define HH 256
#define VV 10000
#define MM (BB*SS)     // 6400
#define NPAD 10240     // VV padded to N-tile multiple

// ---------------- device scratch (no allocs allowed in kernel_launch) ------
__device__ float g_xin[MM * HH];                         // input projection [b][t][j]
__device__ float g_WT[HH * HH];                          // W_hh transposed: [k][j]
// t-MAJOR: row m = t*128 + b ; [m][0:256]=hi, [256:512]=lo
__device__ __align__(16) __nv_bfloat16 g_A2[MM * 512];
__device__ __align__(16) __nv_bfloat16 g_B2[(size_t)NPAD * 512]; // split of W_aff
__device__ int g_prog[SS];                               // per-step producer arrivals

// ---------------- packed fp32x2 helpers --------------------------------------
__device__ __forceinline__ double dup2(float x) {
    double r; asm("mov.b64 %0, {%1, %1};" : "=d"(r) : "f"(x)); return r;
}
__device__ __forceinline__ double pk2(float lo, float hi) {
    double r; asm("mov.b64 %0, {%1, %2};" : "=d"(r) : "f"(lo), "f"(hi)); return r;
}
__device__ __forceinline__ float2 unpk(double d) {
    float2 f; asm("mov.b64 {%0, %1}, %2;" : "=f"(f.x), "=f"(f.y) : "d"(d)); return f;
}
__device__ __forceinline__ void ffma2(double& acc, double a, double b) {
    asm("fma.rn.f32x2 %0, %1, %2, %0;" : "+d"(acc) : "d"(a), "d"(b));
}
__device__ __forceinline__ double fadd2(double a, double b) {
    double r; asm("add.rn.f32x2 %0, %1, %2;" : "=d"(r) : "d"(a), "d"(b)); return r;
}

// ---------------- mma / smem helpers ------------------------------------------
__device__ __forceinline__ uint32_t smem_u32(const void* p) {
    uint32_t a;
    asm("{ .reg .u64 t; cvta.to.shared.u64 t, %1; cvt.u32.u64 %0, t; }" : "=r"(a) : "l"(p));
    return a;
}
__device__ __forceinline__ void cp_async16(uint32_t dst, const void* src) {
    asm volatile("cp.async.cg.shared.global [%0], [%1], 16;"
                 :: "r"(dst), "l"(src) : "memory");
}
__device__ __forceinline__ void ldsm4(uint32_t r[4], uint32_t addr) {
    asm volatile("ldmatrix.sync.aligned.m8n8.x4.shared.b16 {%0,%1,%2,%3}, [%4];"
                 : "=r"(r[0]), "=r"(r[1]), "=r"(r[2]), "=r"(r[3]) : "r"(addr));
}
__device__ __forceinline__ void mma16816(float c[4], const uint32_t a[4],
                                         uint32_t b0, uint32_t b1) {
    asm volatile(
        "mma.sync.aligned.m16n8k16.row.col.f32.bf16.bf16.f32 "
        "{%0,%1,%2,%3}, {%4,%5,%6,%7}, {%8,%9}, {%0,%1,%2,%3};"
        : "+f"(c[0]), "+f"(c[1]), "+f"(c[2]), "+f"(c[3])
        : "r"(a[0]), "r"(a[1]), "r"(a[2]), "r"(a[3]), "r"(b0), "r"(b1));
}
__device__ __forceinline__ int ld_acq(const int* p) {
    int v; asm volatile("ld.acquire.gpu.global.b32 %0, [%1];" : "=r"(v) : "l"(p)); return v;
}
#define SW128(x) ((x) ^ (((x) >> 3) & 0x70))

__device__ __forceinline__ void store_split(__nv_bfloat16* p, float v) {
    __nv_bfloat16 hi = __float2bfloat16(v);
    p[0]   = hi;
    p[256] = __float2bfloat16(v - __bfloat162float(hi));
}

// ============================================================================
// Kernel A (fused prep): embed+proj | split W_aff | transpose W_hh | zero prog
// ============================================================================
#define NB_EMB 200
#define NB_SPL 2560
#define NB_TRA 256
#define NB_PREP (NB_EMB + NB_SPL + NB_TRA)

__global__ void __launch_bounds__(256)
prep(const int* __restrict__ xraw,
     const float* __restrict__ emb,
     const float* __restrict__ W_ih,
     const float* __restrict__ b_ih,
     const float* __restrict__ b_hh,
     const float* __restrict__ W_hh,
     const float* __restrict__ Wa)
{
    const int bb = blockIdx.x;

    if (bb >= NB_EMB + NB_SPL) {                 // ---- transpose W_hh ----
        int idx = (bb - NB_EMB - NB_SPL) * 256 + threadIdx.x;  // 65536 elems
        int k = idx >> 8, j = idx & 255;
        g_WT[k * HH + j] = W_hh[j * HH + k];
        return;
    }
    if (bb >= NB_EMB) {                          // ---- split W_aff ----
        int idx = (bb - NB_EMB) * 256 + threadIdx.x;   // NPAD * 64
        int n  = idx >> 6;
        int k4 = (idx & 63) << 2;
        float4 w = make_float4(0.f, 0.f, 0.f, 0.f);
        if (n < VV) w = *(const float4*)(Wa + (size_t)n * 256 + k4);
        __nv_bfloat16* p = g_B2 + (size_t)n * 512 + k4;
        __nv_bfloat16 h0 = __float2bfloat16(w.x);
        __nv_bfloat16 h1 = __float2bfloat16(w.y);
        __nv_bfloat16 h2 = __float2bfloat16(w.z);
        __nv_bfloat16 h3 = __float2bfloat16(w.w);
        p[0] = h0; p[1] = h1; p[2] = h2; p[3] = h3;
        p[256] = __float2bfloat16(w.x - __bfloat162float(h0));
        p[257] = __float2bfloat16(w.y - __bfloat162float(h1));
        p[258] = __float2bfloat16(w.z - __bfloat162float(h2));
        p[259] = __float2bfloat16(w.w - __bfloat162float(h3));
        return;
    }

    // ---- embedding + input projection ----
    if (bb == 0 && threadIdx.x < SS) g_prog[threadIdx.x] = 0;   // reset progress

    __shared__ __align__(16) float se[32][XX];

    const bool is64 = ((xraw[1] | xraw[3] | xraw[5] | xraw[7] | xraw[9]) == 0) &&
                      ((xraw[0] | xraw[2] | xraw[4] | xraw[6] | xraw[8]) != 0);

    const int m0 = bb * 32;
    for (int i = threadIdx.x; i < 32 * (XX / 4); i += 256) {
        int r = i >> 5, c = i & 31;
        int m = m0 + r;
        int tok = is64 ? xraw[2 * m] : xraw[m];
        ((float4*)se[r])[c] = ((const float4*)(emb + (long long)tok * XX))[c];
    }
    __syncthreads();

    const int j = threadIdx.x;
    const float bias = b_ih[j] + b_hh[j];
    float acc[32];
#pragma unroll
    for (int r = 0; r < 32; r++) acc[r] = bias;

    const float* wr = W_ih + j * XX;
#pragma unroll 4
    for (int k = 0; k < XX; k += 4) {
        float4 w = *(const float4*)(wr + k);
#pragma unroll
        for (int r = 0; r < 32; r++) {
            float4 e = *(const float4*)&se[r][k];
            acc[r] = fmaf(w.x, e.x, fmaf(w.y, e.y, fmaf(w.z, e.z, fmaf(w.w, e.w, acc[r]))));
        }
    }
#pragma unroll
    for (int r = 0; r < 32; r++)
        g_xin[(m0 + r) * HH + j] = acc[r];
}

// ============================================================================
// FUSED kernel, cluster(4):
//   bids 0..63   = RNN producers. 16 clusters x 4 CTAs; cluster owns 8 batch
//                  rows; CTA rank owns 64 output columns, W quarter in smem
//                  (64 KB) + h double-buffer (16 KB) = 80 KB.
//   bids 64..4063 = GEMM consumers, t-major tiles (unchanged internals).
// Unified dynamic smem = 98304 -> 2 CTAs/SM for both roles.
// ============================================================================
#define RNN_W_F2   (128 * 64)            // float2: quarter of W
#define RNN_HB_F2  (2 * 4 * 256)         // [buf][rq][col]
#define TILE_BYTES 16384
#define STAGE_BYTES (2 * TILE_BYTES)
#define NSTAGE 3
#define SMEM_FUSED (NSTAGE * STAGE_BYTES)   // 98304 (rnn uses 80 KB subset)
#define NB_RNN 64
#define NT_N   (NPAD / 128)              // 80 n-tiles per timestep
#define NB_FUSED (NB_RNN + SS * NT_N)    // 64 + 4000 = 4064

__global__ void __launch_bounds__(256, 2) __cluster_dims__(4, 1, 1)
fused_rnn_gemm(const float* __restrict__ ba, float* __restrict__ C)
{
    extern __shared__ __align__(1024) char smem[];
    const int bid = blockIdx.x;
    const int tid = threadIdx.x;

    if (bid < NB_RNN) {
        // ==================== RNN producer (cluster-4) ========================
        float2* wsp = (float2*)smem;            // [k2*64 + jl], k2=0..127
        float2* hb  = (float2*)smem + RNN_W_F2; // [(buf*4 + rq)*256 + col]
        const uint32_t hb_addr = smem_u32(hb);

        const int rq   = tid >> 6;              // rowpair 0..3
        const int jl   = tid & 63;
        const uint32_t rank = bid & 3;
        const int jg   = rank * 64 + jl;        // global output column
        const int b0   = (bid >> 2) * 8;        // 8 batch rows per cluster

        // fill W quarter: wsp[k2][jl] = (WT[2k2][jg], WT[2k2+1][jg])
        for (int i = tid; i < RNN_W_F2; i += 256) {
            int k2 = i >> 6, j = i & 63;
            int jgl = rank * 64 + j;
            wsp[i] = make_float2(g_WT[(2 * k2) * HH + jgl],
                                 g_WT[(2 * k2 + 1) * HH + jgl]);
        }
        // zero h buffer 0
        for (int i = tid; i < 4 * 256; i += 256) hb[i] = make_float2(0.f, 0.f);

        asm volatile("barrier.cluster.arrive.aligned;" ::: "memory");
        asm volatile("barrier.cluster.wait.aligned;" ::: "memory");

        const int r0 = b0 + 2 * rq;
        const float* x0p = g_xin + (size_t)r0 * SS * HH + jg;
        const float* x1p = g_xin + (size_t)(r0 + 1) * SS * HH + jg;
        // t-major A2: row m = t*BB + b
        __nv_bfloat16* a0p = g_A2 + (size_t)r0 * 512 + jg;
        __nv_bfloat16* a1p = g_A2 + (size_t)(r0 + 1) * 512 + jg;

        const float2* wp = wsp + jl;
        const uint32_t p1 = rank ^ 1, p2 = rank ^ 2, p3 = rank ^ 3;

        int cur = 0;
        for (int t = 0; t < SS; ++t) {
            double acc_e = pk2(x0p[(size_t)t * HH], x1p[(size_t)t * HH]);
            double acc_o = 0.0;

            const double2* hc = (const double2*)(hb + (cur * 4 + rq) * 256);
#pragma unroll 8
            for (int k2 = 0; k2 < 128; ++k2) {
                float2 wv  = wp[k2 * 64];
                double2 h2 = hc[k2];
                ffma2(acc_e, dup2(wv.x), h2.x);
                ffma2(acc_o, dup2(wv.y), h2.y);
            }

            float2 f = unpk(fadd2(acc_e, acc_o));
            float h0 = tanhf(f.x), h1 = tanhf(f.y);

            const int nxt = cur ^ 1;
            const long long hp = __double_as_longlong(pk2(h0, h1));
            uint32_t loc = hb_addr + (uint32_t)(((nxt * 4 + rq) * 256 + jg) * 8);
            asm volatile("st.shared.b64 [%0], %1;" :: "r"(loc), "l"(hp) : "memory");
            asm volatile(
                "{\n\t.reg .b32 ra;\n\t"
                "mapa.shared::cluster.u32 ra, %0, %1;\n\t"
                "st.shared::cluster.b64 [ra], %2;\n\t"
                "mapa.shared::cluster.u32 ra, %0, %3;\n\t"
                "st.shared::cluster.b64 [ra], %2;\n\t"
                "mapa.shared::cluster.u32 ra, %0, %4;\n\t"
                "st.shared::cluster.b64 [ra], %2;\n\t}"
                :: "r"(loc), "r"(p1), "l"(hp), "r"(p2), "r"(p3) : "memory");

            store_split(a0p + (size_t)t * (BB * 512), h0);
            store_split(a1p + (size_t)t * (BB * 512), h1);
            __threadfence();   // A2 visible device-wide before signal

            asm volatile("barrier.cluster.arrive.aligned;" ::: "memory");
            asm volatile("barrier.cluster.wait.aligned;" ::: "memory");
            if (tid == 0) atomicAdd(&g_prog[t], 1);
            cur = nxt;
        }
        return;
    }

    // ======================= GEMM consumer ==================================
    const int gid = bid - NB_RNN;
    const int tT  = gid / NT_N;            // timestep tile (M-tile)
    const int bn  = (gid % NT_N) * 128;
    const int bm  = tT * 128;

    // wait for all 64 producers of step tT
    if (tid == 0) {
        while (ld_acq(&g_prog[tT]) < NB_RNN) __nanosleep(256);
    }
    __syncthreads();

    const uint32_t sb = smem_u32(smem);
    const int wid  = tid >> 5;
    const int lane = tid & 31;

    uint32_t t_sw[4];
    const __nv_bfloat16* a_src[4];
    const __nv_bfloat16* b_src[4];
#pragma unroll
    for (int i = 0; i < 4; i++) {
        int idx = i * 256 + tid, row = idx >> 3, c = idx & 7;
        t_sw[i] = SW128(row * 128 + c * 16);
        a_src[i] = g_A2 + (size_t)(bm + row) * 512 + c * 8;
        b_src[i] = g_B2 + (size_t)(bn + row) * 512 + c * 8;
    }

    const int wm0 = (wid >> 1) * 32;
    const int wn0 = (wid & 1) * 64;
    const int a_row  = wm0 + (lane & 7) + ((lane & 8) ? 8 : 0);
    const int a_koff = (lane & 16) ? 16 : 0;
    const int b_row  = wn0 + (lane & 7) + ((lane & 16) ? 8 : 0);
    const int b_koff = (lane & 8) ? 16 : 0;

    float acc[2][8][4];
#pragma unroll
    for (int mt = 0; mt < 2; mt++)
#pragma unroll
        for (int nt = 0; nt < 8; nt++)
#pragma unroll
            for (int q = 0; q < 4; q++) acc[mt][nt][q] = 0.f;

    auto prefetch = [&](int ch) {
        const int seg = ch >> 2, s = ch & 3;
        const int aoff = ((seg == 1) ? 256 : 0) + s * 64;
        const int boff = ((seg == 2) ? 256 : 0) + s * 64;
        const uint32_t base = sb + (ch % NSTAGE) * STAGE_BYTES;
#pragma unroll
        for (int i = 0; i < 4; i++) cp_async16(base + t_sw[i], a_src[i] + aoff);
#pragma unroll
        for (int i = 0; i < 4; i++) cp_async16(base + TILE_BYTES + t_sw[i], b_src[i] + boff);
        asm volatile("cp.async.commit_group;" ::: "memory");
    };

    prefetch(0);
    prefetch(1);

#pragma unroll 1
    for (int ch = 0; ch < 12; ++ch) {
        if (ch < 11) asm volatile("cp.async.wait_group 1;" ::: "memory");
        else         asm volatile("cp.async.wait_group 0;" ::: "memory");
        __syncthreads();
        if (ch + 2 < 12) prefetch(ch + 2);

        const uint32_t Ab = sb + (ch % NSTAGE) * STAGE_BYTES;
        const uint32_t Bb = Ab + TILE_BYTES;

#pragma unroll
        for (int ks = 0; ks < 4; ++ks) {
            const int kb = ks * 32;
            uint32_t a[2][4], b[4][4];
#pragma unroll
            for (int mt = 0; mt < 2; mt++)
                ldsm4(a[mt], Ab + SW128((a_row + mt * 16) * 128 + kb + a_koff));
#pragma unroll
            for (int p = 0; p < 4; p++)
                ldsm4(b[p], Bb + SW128((b_row + p * 16) * 128 + kb + b_koff));
#pragma unroll
            for (int mt = 0; mt < 2; mt++)
#pragma unroll
                for (int p = 0; p < 4; p++) {
                    mma16816(acc[mt][2 * p + 0], a[mt], b[p][0], b[p][1]);
                    mma16816(acc[mt][2 * p + 1], a[mt], b[p][2], b[p][3]);
                }
        }
    }

    // epilogue: C row for tile-local row b is m_orig = b*SS + tT
    const int lm = lane >> 2;
    const int lq = (lane & 3) * 2;
#pragma unroll
    for (int nt = 0; nt < 8; nt++) {
        const int gcol = bn + wn0 + nt * 8 + lq;
        if (gcol >= VV) continue;
        const float2 bv = *(const float2*)(ba + gcol);
#pragma unroll
        for (int mt = 0; mt < 2; mt++) {
            const int brow = wm0 + mt * 16 + lm;             // batch index
            float* c0 = C + ((size_t)brow * SS + tT) * VV + gcol;
            float2 o0 = make_float2(acc[mt][nt][0] + bv.x, acc[mt][nt][1] + bv.y);
            float2 o1 = make_float2(acc[mt][nt][2] + bv.x, acc[mt][nt][3] + bv.y);
            *(float2*)c0                         = o0;
            *(float2*)(c0 + (size_t)8 * SS * VV) = o1;       // brow+8
        }
    }
}

// ============================================================================
extern "C" void kernel_launch(void* const* d_in, const int* in_sizes, int n_in,
                              void* d_out, int out_size)
{
    const int*   x     = (const int*)  d_in[0];
    const float* emb   = (const float*)d_in[1];
    const float* W_ih  = (const float*)d_in[2];
    const float* W_hh  = (const float*)d_in[3];
    const float* b_ih  = (const float*)d_in[4];
    const float* b_hh  = (const float*)d_in[5];
    const float* W_aff = (const float*)d_in[6];
    const float* b_aff = (const float*)d_in[7];
    float* out = (float*)d_out;

    cudaFuncSetAttribute(fused_rnn_gemm, cudaFuncAttributeMaxDynamicSharedMemorySize, SMEM_FUSED);

    prep<<<NB_PREP, 256>>>(x, emb, W_ih, b_ih, b_hh, W_hh, W_aff);
    fused_rnn_gemm<<<NB_FUSED, 256, SMEM_FUSED>>>(b_aff, out);
}